// round 16
// baseline (speedup 1.0000x reference)
#include <cuda_runtime.h>

#define NF    20480
#define NACC  128
#define BATCH 4096
#define REC   132            // 128 acc weights + 2 psqt + 2 pad (528B, 16B aligned)
#define RECV4 33             // REC/4
#define QTR4  (NF / 4 / 4)   // 1280 float4 per quarter-row
#define ITERS (NF / 4 / 512) // 10 iterations of 512 floats per quarter
#define CAP   96             // per-warp active-feature list capacity
#define FULLM 0xffffffffu
#define NTILE (NF / 32)      // 640 32-feature tiles
#define BGRID 148            // slim builder: 1 block/SM during PDL overlap

// Packed feature-major table: g_table[f*132 + s], s<128 -> acc_w[s][f],
// s==128/129 -> psqt_w[0/1][f], s==130/131 -> 0.
__device__ float g_table[(size_t)NF * REC];

// ---------------------------------------------------------------------------
// Kernel 1: zero output + transpose acc_w/psqt_w into g_table.
// Persistent-style slim grid (148 blocks, ~4.3 tiles each): same ~3us duration
// (BW-bound) but only 1 block/SM, so co-launched main-kernel blocks get SM
// residency from t=0 during the PDL overlap window.
// ---------------------------------------------------------------------------
__global__ __launch_bounds__(256) void build_table_kernel(
    const float* __restrict__ acc_w,
    const float* __restrict__ psqt_w,
    float* __restrict__ out)
{
    if (blockIdx.x < 32) out[blockIdx.x * 256 + threadIdx.x] = 0.0f;
    __threadfence();
    cudaTriggerProgrammaticLaunchCompletion();

    __shared__ float tile[32][133];

    for (int tidx = blockIdx.x; tidx < NTILE; tidx += BGRID) {
        const int f0 = tidx * 32;

        for (int idx = threadIdx.x; idx < 32 * REC; idx += 256) {
            int s  = idx >> 5;
            int fl = idx & 31;
            int f  = f0 + fl;
            float v = 0.0f;
            if (s < NACC)      v = acc_w[(size_t)s * NF + f];
            else if (s == 128) v = psqt_w[f];
            else if (s == 129) v = psqt_w[NF + f];
            tile[fl][s] = v;
        }
        __syncthreads();
        for (int idx = threadIdx.x; idx < 32 * REC; idx += 256) {
            int fl = idx / REC;
            int s  = idx - fl * REC;
            g_table[(size_t)(f0 + fl) * REC + s] = tile[fl][s];
        }
        __syncthreads();                 // tile smem reused next iteration
    }
}

// ---------------------------------------------------------------------------
// Kernel 2 (R14 config — best measured): block = (row, side), 128 threads =
// 4 warps, one feature-quarter per warp.
// Phase 1: pure streaming scan; pair ballots (8 floats per ballot) with a
//          packed mask8 -> single shfl per hit source lane.
// Grid sync (builder overlapped via PDL trigger).
// Phase 2: MLP-4 batched L2 gather, quarter merge, clip + output layer,
//          atomicAdd(+/-) into out[row] (exactly 2 adds/element: deterministic).
// ---------------------------------------------------------------------------
__global__ __launch_bounds__(128, 10) void nnue_main_kernel(
    const float* __restrict__ white,
    const float* __restrict__ black,
    const float* __restrict__ acc_b,
    const float* __restrict__ out_w,
    float* __restrict__ out)
{
    const int tid  = threadIdx.x;
    const int q    = tid >> 5;          // warp = feature quarter, 0..3
    const int lane = tid & 31;
    const int side = blockIdx.x & 1;    // 0=white, 1=black
    const int row  = blockIdx.x >> 1;

    // explicit 16B alignment — accessed via float4 casts
    __shared__ __align__(16) float s_acc[4][NACC]; // per-quarter partials
    __shared__ __align__(16) int   s_idx[4][CAP];  // per-warp active features
    __shared__ __align__(16) float s_ps[4][2];     // per-quarter psqt partials

    const float* base_ptr = (side == 0 ? white : black);
    const uint4* __restrict__ rowp =
        reinterpret_cast<const uint4*>(base_ptr + (size_t)row * NF) + q * QTR4;
    const int fbase4 = q * QTR4;

    // ================= Phase 1: streaming scan =================
    int cnt = 0;                        // warp-uniform

    uint4 q0 = __ldcs(rowp + lane);
    uint4 q1 = __ldcs(rowp + lane + 32);
    uint4 q2 = __ldcs(rowp + lane + 64);
    uint4 q3 = __ldcs(rowp + lane + 96);

    #pragma unroll 1
    for (int it = 0; it < ITERS; ++it) {
        uint4 n0, n1, n2, n3;
        if (it + 1 < ITERS) {
            const int b4 = (it + 1) * 128 + lane;
            n0 = __ldcs(rowp + b4);
            n1 = __ldcs(rowp + b4 + 32);
            n2 = __ldcs(rowp + b4 + 64);
            n3 = __ldcs(rowp + b4 + 96);
        }

        // pair-ballot: test 8 floats (two float4 groups) per ballot
        #pragma unroll
        for (int u = 0; u < 2; ++u) {
            uint4 qa = (u == 0) ? q0 : q2;
            uint4 qb = (u == 0) ? q1 : q3;
            // inputs are exactly 0.0f or 1.0f -> integer nonzero test is exact
            unsigned orw = qa.x | qa.y | qa.z | qa.w
                         | qb.x | qb.y | qb.z | qb.w;
            unsigned any_m = __ballot_sync(FULLM, orw != 0u);
            if (any_m) {                        // warp-uniform rare path (~32%)
                unsigned mask8 = (unsigned)(qa.x != 0u)
                               | ((unsigned)(qa.y != 0u) << 1)
                               | ((unsigned)(qa.z != 0u) << 2)
                               | ((unsigned)(qa.w != 0u) << 3)
                               | ((unsigned)(qb.x != 0u) << 4)
                               | ((unsigned)(qb.y != 0u) << 5)
                               | ((unsigned)(qb.z != 0u) << 6)
                               | ((unsigned)(qb.w != 0u) << 7);
                do {
                    int src = __ffs(any_m) - 1;
                    any_m &= any_m - 1;
                    unsigned m8 = __shfl_sync(FULLM, mask8, src);
                    while (m8) {
                        int c = __ffs(m8) - 1;   // 0..7
                        m8 &= m8 - 1;
                        // group c>>2 selects qa (0) vs qb (1); qb is 32
                        // float4s after qa within this iteration.
                        int f4 = it * 128 + (u * 2 + (c >> 2)) * 32 + src;
                        int j  = 4 * (fbase4 + f4) + (c & 3);
                        if (lane == 0 && cnt < CAP) s_idx[q][cnt] = j;
                        ++cnt;
                    }
                } while (any_m);
            }
        }
        q0 = n0; q1 = n1; q2 = n2; q3 = n3;
    }
    if (cnt > CAP) cnt = CAP;
    __syncwarp();                        // make s_idx visible to whole warp

    // builder finished long ago (PDL overlap); returns immediately
    cudaGridDependencySynchronize();

    // ================= Phase 2: batched gather, MLP=4 =================
    const float4* __restrict__ tbl = reinterpret_cast<const float4*>(g_table);

    float ax, ay, az, aw;
    if (q == 0) {
        float4 b = reinterpret_cast<const float4*>(acc_b)[lane];
        ax = b.x; ay = b.y; az = b.z; aw = b.w;
    } else {
        ax = ay = az = aw = 0.0f;
    }
    float p0 = 0.0f, p1 = 0.0f;          // psqt partials (lanes 0..3)

    int i = 0;
    #pragma unroll 1
    for (; i + 4 <= cnt; i += 4) {       // four independent L2 loads in flight
        int j0 = s_idx[q][i];
        int j1 = s_idx[q][i + 1];
        int j2 = s_idx[q][i + 2];
        int j3 = s_idx[q][i + 3];
        float4 t0 = tbl[(size_t)j0 * RECV4 + lane];
        float4 t1 = tbl[(size_t)j1 * RECV4 + lane];
        float4 t2 = tbl[(size_t)j2 * RECV4 + lane];
        float4 t3 = tbl[(size_t)j3 * RECV4 + lane];
        if (lane < 4) {                  // lane L handles psqt of j(i+L)
            int jp = s_idx[q][i + lane];
            float4 pq = tbl[(size_t)jp * RECV4 + 32];
            p0 += pq.x; p1 += pq.y;
        }
        ax += t0.x; ay += t0.y; az += t0.z; aw += t0.w;
        ax += t1.x; ay += t1.y; az += t1.z; aw += t1.w;
        ax += t2.x; ay += t2.y; az += t2.z; aw += t2.w;
        ax += t3.x; ay += t3.y; az += t3.z; aw += t3.w;
    }
    #pragma unroll 1
    for (; i < cnt; ++i) {               // remainder (0..3)
        int j0 = s_idx[q][i];
        float4 t0 = tbl[(size_t)j0 * RECV4 + lane];
        if (lane == 0) {
            float4 pq = tbl[(size_t)j0 * RECV4 + 32];
            p0 += pq.x; p1 += pq.y;
        }
        ax += t0.x; ay += t0.y; az += t0.z; aw += t0.w;
    }
    // reduce psqt partials (live in lanes 0..3) across the warp
    #pragma unroll
    for (int off = 16; off > 0; off >>= 1) {
        p0 += __shfl_xor_sync(FULLM, p0, off);
        p1 += __shfl_xor_sync(FULLM, p1, off);
    }

    // ---- publish partial accumulators (merge BEFORE clip) ----
    reinterpret_cast<float4*>(&s_acc[q][0])[lane] = make_float4(ax, ay, az, aw);
    if (lane == 0) { s_ps[q][0] = p0; s_ps[q][1] = p1; }
    __syncthreads();

    // ---- warp 0: reduce quarters, clip, output layer, signed atomic ----
    if (q == 0) {
        float4 a0 = reinterpret_cast<const float4*>(&s_acc[0][0])[lane];
        float4 a1 = reinterpret_cast<const float4*>(&s_acc[1][0])[lane];
        float4 a2 = reinterpret_cast<const float4*>(&s_acc[2][0])[lane];
        float4 a3 = reinterpret_cast<const float4*>(&s_acc[3][0])[lane];
        float rx = a0.x + a1.x + a2.x + a3.x;
        float ry = a0.y + a1.y + a2.y + a3.y;
        float rz = a0.z + a1.z + a2.z + a3.z;
        float rw = a0.w + a1.w + a2.w + a3.w;

        rx = fminf(fmaxf(rx, 0.0f), 1.0f);
        ry = fminf(fmaxf(ry, 0.0f), 1.0f);
        rz = fminf(fmaxf(rz, 0.0f), 1.0f);
        rw = fminf(fmaxf(rw, 0.0f), 1.0f);

        const float4 ow0 = reinterpret_cast<const float4*>(out_w)[lane];
        const float4 ow1 = reinterpret_cast<const float4*>(out_w)[32 + lane];
        float s0 = rx * ow0.x + ry * ow0.y + rz * ow0.z + rw * ow0.w;
        float s1 = rx * ow1.x + ry * ow1.y + rz * ow1.z + rw * ow1.w;
        #pragma unroll
        for (int off = 16; off > 0; off >>= 1) {
            s0 += __shfl_xor_sync(FULLM, s0, off);
            s1 += __shfl_xor_sync(FULLM, s1, off);
        }
        if (lane == 0) {
            float pp0 = s_ps[0][0] + s_ps[1][0] + s_ps[2][0] + s_ps[3][0];
            float pp1 = s_ps[0][1] + s_ps[1][1] + s_ps[2][1] + s_ps[3][1];
            const float sgn = (side == 0) ? 1.0f : -1.0f;
            // exactly two adds per element (+white, -black): commutative
            // -> bitwise deterministic regardless of scheduling order.
            atomicAdd(&out[row * 2 + 0], sgn * (pp0 + s0));
            atomicAdd(&out[row * 2 + 1], sgn * (pp1 + s1));
        }
    }
}

// ---------------------------------------------------------------------------
extern "C" void kernel_launch(void* const* d_in, const int* in_sizes, int n_in,
                              void* d_out, int out_size)
{
    const float* white  = (const float*)d_in[0];
    const float* black  = (const float*)d_in[1];
    const float* psqt_w = (const float*)d_in[2];
    const float* acc_w  = (const float*)d_in[3];
    const float* acc_b  = (const float*)d_in[4];
    const float* out_w  = (const float*)d_in[5];
    (void)in_sizes; (void)n_in; (void)out_size;

    build_table_kernel<<<BGRID, 256>>>(acc_w, psqt_w, (float*)d_out);

    // PDL: builder zeroes out + triggers at entry; main kernel co-schedules,
    // streams inputs during the builder, grid-syncs before first table gather.
    cudaLaunchConfig_t cfg = {};
    cfg.gridDim  = dim3(BATCH * 2);
    cfg.blockDim = dim3(128);
    cfg.dynamicSmemBytes = 0;
    cfg.stream = 0;
    cudaLaunchAttribute attrs[1];
    attrs[0].id = cudaLaunchAttributeProgrammaticStreamSerialization;
    attrs[0].val.programmaticStreamSerializationAllowed = 1;
    cfg.attrs = attrs;
    cfg.numAttrs = 1;
    cudaLaunchKernelEx(&cfg, nnue_main_kernel,
                       white, black, acc_b, out_w, (float*)d_out);
}

// round 17
// speedup vs baseline: 1.1630x; 1.1630x over previous
#include <cuda_runtime.h>

#define NF    20480
#define NACC  128
#define BATCH 4096
#define REC   132            // 128 acc weights + 2 psqt + 2 pad (528B, 16B aligned)
#define RECV4 33             // REC/4
#define QTR4  (NF / 4 / 4)   // 1280 float4 per quarter-row
#define ITERS (NF / 4 / 512) // 10 iterations of 512 floats per quarter
#define CAP   96             // per-warp active-feature list capacity
#define FULLM 0xffffffffu

// Packed feature-major table: g_table[f*132 + s], s<128 -> acc_w[s][f],
// s==128/129 -> psqt_w[0/1][f], s==130/131 -> 0.
__device__ float g_table[(size_t)NF * REC];

// ---------------------------------------------------------------------------
// Kernel 1: zero output + transpose acc_w [128,20480] + psqt_w [2,20480] into
// g_table. 640 blocks (burst parallelism keeps the PDL overlap window ~3us;
// the slim-builder experiment R16 showed fewer blocks get BW-starved by the
// co-launched main kernel and serialize the whole launch).
// Zero ordered before PDL trigger (threadfence) -> visible to main kernel.
// ---------------------------------------------------------------------------
__global__ __launch_bounds__(256) void build_table_kernel(
    const float* __restrict__ acc_w,
    const float* __restrict__ psqt_w,
    float* __restrict__ out)
{
    if (blockIdx.x < 32) out[blockIdx.x * 256 + threadIdx.x] = 0.0f;
    __threadfence();
    cudaTriggerProgrammaticLaunchCompletion();

    __shared__ float tile[32][133];
    const int f0 = blockIdx.x * 32;

    for (int idx = threadIdx.x; idx < 32 * REC; idx += 256) {
        int s  = idx >> 5;
        int fl = idx & 31;
        int f  = f0 + fl;
        float v = 0.0f;
        if (s < NACC)      v = acc_w[(size_t)s * NF + f];
        else if (s == 128) v = psqt_w[f];
        else if (s == 129) v = psqt_w[NF + f];
        tile[fl][s] = v;
    }
    __syncthreads();
    for (int idx = threadIdx.x; idx < 32 * REC; idx += 256) {
        int fl = idx / REC;
        int s  = idx - fl * REC;
        g_table[(size_t)(f0 + fl) * REC + s] = tile[fl][s];
    }
}

// ---------------------------------------------------------------------------
// Kernel 2 (R11 configuration — wall-clock best across the session):
// block = (row, side), 128 threads = 4 warps, one feature-quarter per warp.
// Phase 1: pure streaming scan (integer nonzero tests, lazy mask) -> index
//          list in smem; DRAM requests never stall behind L2 gather chains.
// Grid sync (builder overlapped via PDL trigger).
// Phase 2: MLP-4 batched L2 gather, quarter merge, clip + output layer,
//          atomicAdd(+/-) into out[row] (exactly 2 adds/element: deterministic).
// ---------------------------------------------------------------------------
__global__ __launch_bounds__(128, 10) void nnue_main_kernel(
    const float* __restrict__ white,
    const float* __restrict__ black,
    const float* __restrict__ acc_b,
    const float* __restrict__ out_w,
    float* __restrict__ out)
{
    const int tid  = threadIdx.x;
    const int q    = tid >> 5;          // warp = feature quarter, 0..3
    const int lane = tid & 31;
    const int side = blockIdx.x & 1;    // 0=white, 1=black
    const int row  = blockIdx.x >> 1;

    // explicit 16B alignment — accessed via float4 casts
    __shared__ __align__(16) float s_acc[4][NACC]; // per-quarter partials
    __shared__ __align__(16) int   s_idx[4][CAP];  // per-warp active features
    __shared__ __align__(16) float s_ps[4][2];     // per-quarter psqt partials

    const float* base_ptr = (side == 0 ? white : black);
    const uint4* __restrict__ rowp =
        reinterpret_cast<const uint4*>(base_ptr + (size_t)row * NF) + q * QTR4;
    const int fbase4 = q * QTR4;

    // ================= Phase 1: streaming scan =================
    int cnt = 0;                        // warp-uniform

    uint4 q0 = __ldcs(rowp + lane);
    uint4 q1 = __ldcs(rowp + lane + 32);
    uint4 q2 = __ldcs(rowp + lane + 64);
    uint4 q3 = __ldcs(rowp + lane + 96);

    #pragma unroll 1
    for (int it = 0; it < ITERS; ++it) {
        uint4 n0, n1, n2, n3;
        if (it + 1 < ITERS) {
            const int b4 = (it + 1) * 128 + lane;
            n0 = __ldcs(rowp + b4);
            n1 = __ldcs(rowp + b4 + 32);
            n2 = __ldcs(rowp + b4 + 64);
            n3 = __ldcs(rowp + b4 + 96);
        }

        #pragma unroll
        for (int u = 0; u < 4; ++u) {
            uint4 qq = (u == 0) ? q0 : (u == 1) ? q1 : (u == 2) ? q2 : q3;
            // inputs are exactly 0.0f or 1.0f -> integer nonzero test is exact
            unsigned orw = qq.x | qq.y | qq.z | qq.w;
            unsigned any_m = __ballot_sync(FULLM, orw != 0u);
            if (any_m) {                        // warp-uniform rare path
                unsigned mask4 = (unsigned)(qq.x != 0u)
                               | ((unsigned)(qq.y != 0u) << 1)
                               | ((unsigned)(qq.z != 0u) << 2)
                               | ((unsigned)(qq.w != 0u) << 3);
                do {
                    int src = __ffs(any_m) - 1;
                    any_m &= any_m - 1;
                    unsigned m4 = __shfl_sync(FULLM, mask4, src);
                    int bj = 4 * (fbase4 + it * 128 + 32 * u + src);
                    while (m4) {
                        int c = __ffs(m4) - 1;
                        m4 &= m4 - 1;
                        if (lane == 0 && cnt < CAP) s_idx[q][cnt] = bj + c;
                        ++cnt;
                    }
                } while (any_m);
            }
        }
        q0 = n0; q1 = n1; q2 = n2; q3 = n3;
    }
    if (cnt > CAP) cnt = CAP;
    __syncwarp();                        // make s_idx visible to whole warp

    // builder finished long ago (PDL overlap); returns immediately
    cudaGridDependencySynchronize();

    // ================= Phase 2: batched gather, MLP=4 =================
    const float4* __restrict__ tbl = reinterpret_cast<const float4*>(g_table);

    float ax, ay, az, aw;
    if (q == 0) {
        float4 b = reinterpret_cast<const float4*>(acc_b)[lane];
        ax = b.x; ay = b.y; az = b.z; aw = b.w;
    } else {
        ax = ay = az = aw = 0.0f;
    }
    float p0 = 0.0f, p1 = 0.0f;          // psqt partials (lanes 0..3)

    int i = 0;
    #pragma unroll 1
    for (; i + 4 <= cnt; i += 4) {       // four independent L2 loads in flight
        int j0 = s_idx[q][i];
        int j1 = s_idx[q][i + 1];
        int j2 = s_idx[q][i + 2];
        int j3 = s_idx[q][i + 3];
        float4 t0 = tbl[(size_t)j0 * RECV4 + lane];
        float4 t1 = tbl[(size_t)j1 * RECV4 + lane];
        float4 t2 = tbl[(size_t)j2 * RECV4 + lane];
        float4 t3 = tbl[(size_t)j3 * RECV4 + lane];
        if (lane < 4) {                  // lane L handles psqt of j(i+L)
            int jp = s_idx[q][i + lane];
            float4 pq = tbl[(size_t)jp * RECV4 + 32];
            p0 += pq.x; p1 += pq.y;
        }
        ax += t0.x; ay += t0.y; az += t0.z; aw += t0.w;
        ax += t1.x; ay += t1.y; az += t1.z; aw += t1.w;
        ax += t2.x; ay += t2.y; az += t2.z; aw += t2.w;
        ax += t3.x; ay += t3.y; az += t3.z; aw += t3.w;
    }
    #pragma unroll 1
    for (; i < cnt; ++i) {               // remainder (0..3)
        int j0 = s_idx[q][i];
        float4 t0 = tbl[(size_t)j0 * RECV4 + lane];
        if (lane == 0) {
            float4 pq = tbl[(size_t)j0 * RECV4 + 32];
            p0 += pq.x; p1 += pq.y;
        }
        ax += t0.x; ay += t0.y; az += t0.z; aw += t0.w;
    }
    // reduce psqt partials (live in lanes 0..3) across the warp
    #pragma unroll
    for (int off = 16; off > 0; off >>= 1) {
        p0 += __shfl_xor_sync(FULLM, p0, off);
        p1 += __shfl_xor_sync(FULLM, p1, off);
    }

    // ---- publish partial accumulators (merge BEFORE clip) ----
    reinterpret_cast<float4*>(&s_acc[q][0])[lane] = make_float4(ax, ay, az, aw);
    if (lane == 0) { s_ps[q][0] = p0; s_ps[q][1] = p1; }
    __syncthreads();

    // ---- warp 0: reduce quarters, clip, output layer, signed atomic ----
    if (q == 0) {
        float4 a0 = reinterpret_cast<const float4*>(&s_acc[0][0])[lane];
        float4 a1 = reinterpret_cast<const float4*>(&s_acc[1][0])[lane];
        float4 a2 = reinterpret_cast<const float4*>(&s_acc[2][0])[lane];
        float4 a3 = reinterpret_cast<const float4*>(&s_acc[3][0])[lane];
        float rx = a0.x + a1.x + a2.x + a3.x;
        float ry = a0.y + a1.y + a2.y + a3.y;
        float rz = a0.z + a1.z + a2.z + a3.z;
        float rw = a0.w + a1.w + a2.w + a3.w;

        rx = fminf(fmaxf(rx, 0.0f), 1.0f);
        ry = fminf(fmaxf(ry, 0.0f), 1.0f);
        rz = fminf(fmaxf(rz, 0.0f), 1.0f);
        rw = fminf(fmaxf(rw, 0.0f), 1.0f);

        const float4 ow0 = reinterpret_cast<const float4*>(out_w)[lane];
        const float4 ow1 = reinterpret_cast<const float4*>(out_w)[32 + lane];
        float s0 = rx * ow0.x + ry * ow0.y + rz * ow0.z + rw * ow0.w;
        float s1 = rx * ow1.x + ry * ow1.y + rz * ow1.z + rw * ow1.w;
        #pragma unroll
        for (int off = 16; off > 0; off >>= 1) {
            s0 += __shfl_xor_sync(FULLM, s0, off);
            s1 += __shfl_xor_sync(FULLM, s1, off);
        }
        if (lane == 0) {
            float pp0 = s_ps[0][0] + s_ps[1][0] + s_ps[2][0] + s_ps[3][0];
            float pp1 = s_ps[0][1] + s_ps[1][1] + s_ps[2][1] + s_ps[3][1];
            const float sgn = (side == 0) ? 1.0f : -1.0f;
            // exactly two adds per element (+white, -black): commutative
            // -> bitwise deterministic regardless of scheduling order.
            atomicAdd(&out[row * 2 + 0], sgn * (pp0 + s0));
            atomicAdd(&out[row * 2 + 1], sgn * (pp1 + s1));
        }
    }
}

// ---------------------------------------------------------------------------
extern "C" void kernel_launch(void* const* d_in, const int* in_sizes, int n_in,
                              void* d_out, int out_size)
{
    const float* white  = (const float*)d_in[0];
    const float* black  = (const float*)d_in[1];
    const float* psqt_w = (const float*)d_in[2];
    const float* acc_w  = (const float*)d_in[3];
    const float* acc_b  = (const float*)d_in[4];
    const float* out_w  = (const float*)d_in[5];
    (void)in_sizes; (void)n_in; (void)out_size;

    build_table_kernel<<<NF / 32, 256>>>(acc_w, psqt_w, (float*)d_out);

    // PDL: builder zeroes out + triggers at entry; main kernel co-schedules,
    // streams inputs during the builder, grid-syncs before first table gather.
    cudaLaunchConfig_t cfg = {};
    cfg.gridDim  = dim3(BATCH * 2);
    cfg.blockDim = dim3(128);
    cfg.dynamicSmemBytes = 0;
    cfg.stream = 0;
    cudaLaunchAttribute attrs[1];
    attrs[0].id = cudaLaunchAttributeProgrammaticStreamSerialization;
    attrs[0].val.programmaticStreamSerializationAllowed = 1;
    cfg.attrs = attrs;
    cfg.numAttrs = 1;
    cudaLaunchKernelEx(&cfg, nnue_main_kernel,
                       white, black, acc_b, out_w, (float*)d_out);
}